// round 12
// baseline (speedup 1.0000x reference)
#include <cuda_runtime.h>

// CountVectorizer == per-row bincount over vocab followed by counts @ W + b.
//   out[b, :] = bias + sum_t W[token_ids[b, t], :]   (embedding gather-sum)
//
// Ledger (same total gather bytes, one resident wave):
//   float4 25tok/warp unroll5 (R1) : 12.4 us
//   float2 50tok/warp unroll5 (R6) : 11.33 us
//   float2 50tok/warp unroll10(R10): 12.29 us
//   float1 100tok/warp        (R8/9): 14.37 us
//   R6 + .cg L1-bypass        (R11): 11.296 us  <- champion
// Model: cost/warp ~ within-LDG replay (2.07 cyc/wf trailing wf) + dynamic
// instr stream; float2 is the width optimum, 50 tok/warp is forced by the
// one-wave thread budget. Unroll depth trend (10 -> 5 improved) says front-
// batch depth (oe*MLP_p1 queue contention) still costs; this round follows
// it to unroll 2 (~4 front-batched wf, ~110 outstanding LDG/SM still covers
// the ~220-cyc warm L2 round trip). Also stages pre-scaled row offsets
// (id*64) to drop the per-gather IMAD.

#define CV_BATCH  1024
#define CV_SEQ    200
#define CV_D      128               // d_model
#define CV_D2     (CV_D / 2)        // 64 float2 per full row
#define CV_HALF2  32                // float2 per half row (256 B)
#define CV_WARPS  4

__global__ __launch_bounds__(128)
void count_vectorizer_kernel(const int* __restrict__ token_ids,
                             const float2* __restrict__ W2,
                             const float2* __restrict__ bias2,
                             float2* __restrict__ out2)
{
    __shared__ int    s_off[CV_SEQ];     // pre-scaled: id * CV_D2
    __shared__ float2 s_acc[CV_WARPS][CV_HALF2];

    const int b = blockIdx.x >> 1;        // batch row
    const int h = blockIdx.x & 1;         // d-half (0: floats 0..63, 1: 64..127)

    // Stage this row's 200 token row-offsets (2 coalesced rounds of 128).
    for (int i = threadIdx.x; i < CV_SEQ; i += 128)
        s_off[i] = token_ids[b * CV_SEQ + i] * CV_D2;
    __syncthreads();

    const int lane = threadIdx.x & 31;    // float2 slice within the half-row
    const int w    = threadIdx.x >> 5;    // warp id 0..3 (token stream)
    const int dcol = h * CV_HALF2 + lane; // float2 column in the full row

    float2 acc = make_float2(0.f, 0.f);

    // 50 gathers per warp; unroll 2 = shallow front-batch (~4 wf), enough
    // in-flight chip-wide to cover warm-L2 latency. .cg: no L1 allocation
    // (random-gathered lines are never reused in L1).
    #pragma unroll 2
    for (int t = w; t < CV_SEQ; t += CV_WARPS) {
        const float2 v = __ldcg(&W2[s_off[t] + dcol]);
        acc.x += v.x; acc.y += v.y;
    }

    s_acc[w][lane] = acc;
    __syncthreads();

    // Warp 0 folds the 4 partials, adds bias, stores the 256B half-row.
    if (w == 0) {
        float2 a = s_acc[0][lane];
        #pragma unroll
        for (int g = 1; g < CV_WARPS; g++) {
            const float2 v = s_acc[g][lane];
            a.x += v.x; a.y += v.y;
        }
        const float2 bb = __ldg(&bias2[dcol]);
        a.x += bb.x; a.y += bb.y;
        out2[b * CV_D2 + dcol] = a;
    }
}

extern "C" void kernel_launch(void* const* d_in, const int* in_sizes, int n_in,
                              void* d_out, int out_size)
{
    const int*   token_ids = (const int*)d_in[0];      // [1024, 200] int32
    const float* W         = (const float*)d_in[1];    // [100000, 128] f32
    const float* bias      = (const float*)d_in[2];    // [128] f32
    float*       out       = (float*)d_out;            // [1024, 128] f32

    (void)in_sizes; (void)n_in; (void)out_size;

    count_vectorizer_kernel<<<2 * CV_BATCH, 128>>>(
        token_ids,
        reinterpret_cast<const float2*>(W),
        reinterpret_cast<const float2*>(bias),
        reinterpret_cast<float2*>(out));
}